// round 13
// baseline (speedup 1.0000x reference)
#include <cuda_runtime.h>
#include <cuda_bf16.h>
#include <cuda_fp16.h>
#include <math.h>
#include <stdint.h>

// Problem constants
#define BB 2
#define MM 2048
#define DD 1024
#define HH 16
#define DH 64
#define FF 2624
#define NTOK (BB*MM)           // 4096
#define QKV_N (3*DD)           // 3072
#define WI_N (2*FF)            // 5248

// ---------------- scratch (device globals; no allocation allowed) -------------
__device__ float g_xres[NTOK*DD];
__device__ float2 g_rope[MM*32];
// f16 buffers
__device__ __align__(128) __half g_xh [(size_t)NTOK*DD];     // LN1/attn/LN2 out
__device__ __align__(128) __half g_wh [(size_t)WI_N*DD];     // current weight, f16
__device__ __align__(128) __half g_act[(size_t)NTOK*FF];     // geglu out f16
__device__ __align__(128) __half g_q2[(size_t)BB*HH*MM*DH];
__device__ __align__(128) __half g_k2[(size_t)BB*HH*MM*DH];
__device__ __align__(128) __half g_v2[(size_t)BB*HH*MM*DH];

// ---------------- PTX helpers ---------------------------------------------------
__device__ __forceinline__ uint32_t smem_u32(const void* p) {
    uint32_t a;
    asm("{ .reg .u64 t; cvta.to.shared.u64 t, %1; cvt.u32.u64 %0, t; }"
        : "=r"(a) : "l"(p));
    return a;
}
__device__ __forceinline__ void cp16(uint32_t saddr, const void* g) {
    asm volatile("cp.async.cg.shared.global [%0], [%1], 16;" :: "r"(saddr), "l"(g));
}
__device__ __forceinline__ void ldm_x4(uint32_t* r, uint32_t addr) {
    asm volatile("ldmatrix.sync.aligned.m8n8.x4.shared.b16 {%0,%1,%2,%3}, [%4];"
        : "=r"(r[0]), "=r"(r[1]), "=r"(r[2]), "=r"(r[3]) : "r"(addr));
}
__device__ __forceinline__ void ldm_x4_t(uint32_t* r, uint32_t addr) {
    asm volatile("ldmatrix.sync.aligned.m8n8.x4.trans.shared.b16 {%0,%1,%2,%3}, [%4];"
        : "=r"(r[0]), "=r"(r[1]), "=r"(r[2]), "=r"(r[3]) : "r"(addr));
}
__device__ __forceinline__ void mma16816h(float* c, const uint32_t* a, const uint32_t* b) {
    asm volatile("mma.sync.aligned.m16n8k16.row.col.f32.f16.f16.f32 "
        "{%0,%1,%2,%3}, {%4,%5,%6,%7}, {%8,%9}, {%0,%1,%2,%3};"
        : "+f"(c[0]), "+f"(c[1]), "+f"(c[2]), "+f"(c[3])
        : "r"(a[0]), "r"(a[1]), "r"(a[2]), "r"(a[3]), "r"(b[0]), "r"(b[1]));
}
__device__ __forceinline__ uint32_t cvt_h2(float hi, float lo) {
    uint32_t d;
    asm("cvt.rn.f16x2.f32 %0, %1, %2;" : "=r"(d) : "f"(hi), "f"(lo));
    return d;
}
__device__ __forceinline__ uint32_t h2exp2(uint32_t x) {
    uint32_t d;
    asm("ex2.approx.f16x2 %0, %1;" : "=r"(d) : "r"(x));
    return d;
}

// ---------------- weight convert fp32 -> f16 -----------------------------------
__global__ void cvth_kernel(const float* __restrict__ X, __half* __restrict__ Y, int total)
{
    int i = blockIdx.x * 256 + threadIdx.x;
    if (i < total) Y[i] = __float2half(X[i]);
}

// ---------------- RoPE table ----------------------------------------------------
__global__ void ropetab_kernel(float2* __restrict__ tab)
{
    int gid = blockIdx.x * 256 + threadIdx.x;     // over MM*32
    int i = gid & 31;
    int m = gid >> 5;
    float invf = (float)exp2(-(double)i * (13.287712379549449 / 32.0));
    float angle = (float)m * invf;
    float sv, cv;
    sincosf(angle, &sv, &cv);
    tab[gid] = make_float2(cv, sv);
}

// ---------------- shared GEMM config (128x128, 4-stage) -------------------------
#define PADK 40
#define STAGES 4
#define AB_BYTES (128*PADK*2)               // 10240
#define STAGE_BYTES (2*AB_BYTES)            // 20480
#define BG_SMEM (STAGES*STAGE_BYTES)        // 81920
#define QSCALE 0.18033688011112042f         // 0.125 * log2(e)

// GEMM mainloop macro body (shared by all three gemm kernels)
#define GEMM_MAINLOOP(AGPTR, WROW_EXPR)                                            \
    const int ldr0 = tid >> 2, ldc0 = (tid & 3) * 8;                               \
    const int ldr1 = (tid + 256) >> 2;                                             \
    const uint32_t so0 = (uint32_t)(ldr0*PADK + ldc0) * 2;                         \
    const uint32_t so1 = (uint32_t)(ldr1*PADK + ldc0) * 2;                         \
    float acc[2][8][4];                                                            \
    _Pragma("unroll")                                                              \
    for (int i = 0; i < 2; i++)                                                    \
        _Pragma("unroll")                                                          \
        for (int j = 0; j < 8; j++)                                                \
            _Pragma("unroll")                                                      \
            for (int x = 0; x < 4; x++) acc[i][j][x] = 0.f;                        \
    const int aRowOff0 = (wm*32 + (lid & 15)) * PADK + (lid >> 4) * 8;             \
    const int aRowOff1 = aRowOff0 + 16 * PADK;                                     \
    const int bRowBase = (wn*64 + ((lid >> 4) & 1) * 8 + (lid & 7)) * PADK         \
                       + ((lid >> 3) & 1) * 8;                                     \
    _Pragma("unroll")                                                              \
    for (int t = 0; t < STAGES - 1; t++) {                                         \
        uint32_t sb = base + (uint32_t)t * STAGE_BYTES;                            \
        cp16(sb + so0,            AGPTR + (size_t)ldr0*K3 + t*32 + ldc0);          \
        cp16(sb + AB_BYTES + so0, WROW_EXPR(ldr0) + t*32 + ldc0);                  \
        cp16(sb + so1,            AGPTR + (size_t)ldr1*K3 + t*32 + ldc0);          \
        cp16(sb + AB_BYTES + so1, WROW_EXPR(ldr1) + t*32 + ldc0);                  \
        asm volatile("cp.async.commit_group;");                                    \
    }                                                                              \
    for (int t = 0; t < ntiles; t++) {                                             \
        asm volatile("cp.async.wait_group %0;" :: "n"(STAGES - 2));                \
        __syncthreads();                                                           \
        if (t + STAGES - 1 < ntiles) {                                             \
            int tp = t + STAGES - 1;                                               \
            uint32_t sb = base + (uint32_t)(tp & (STAGES-1)) * STAGE_BYTES;        \
            cp16(sb + so0,            AGPTR + (size_t)ldr0*K3 + tp*32 + ldc0);     \
            cp16(sb + AB_BYTES + so0, WROW_EXPR(ldr0) + tp*32 + ldc0);             \
            cp16(sb + so1,            AGPTR + (size_t)ldr1*K3 + tp*32 + ldc0);     \
            cp16(sb + AB_BYTES + so1, WROW_EXPR(ldr1) + tp*32 + ldc0);             \
        }                                                                          \
        asm volatile("cp.async.commit_group;");                                    \
        uint32_t aS = base + (uint32_t)(t & (STAGES-1)) * STAGE_BYTES;             \
        uint32_t bS = aS + AB_BYTES;                                               \
        _Pragma("unroll")                                                          \
        for (int ks = 0; ks < 2; ks++) {                                           \
            uint32_t afr[2][4];                                                    \
            ldm_x4(afr[0], aS + (uint32_t)(aRowOff0 + ks*16) * 2);                 \
            ldm_x4(afr[1], aS + (uint32_t)(aRowOff1 + ks*16) * 2);                 \
            uint32_t bfr[4][4];                                                    \
            _Pragma("unroll")                                                      \
            for (int np = 0; np < 4; np++)                                         \
                ldm_x4(bfr[np], bS + (uint32_t)(bRowBase + np*16*PADK + ks*16) * 2); \
            _Pragma("unroll")                                                      \
            for (int mt = 0; mt < 2; mt++)                                         \
                _Pragma("unroll")                                                  \
                for (int np = 0; np < 4; np++) {                                   \
                    mma16816h(acc[mt][2*np],     afr[mt], &bfr[np][0]);            \
                    mma16816h(acc[mt][2*np + 1], afr[mt], &bfr[np][2]);            \
                }                                                                  \
        }                                                                          \
    }

// ---------------- QKV GEMM + bias + fused RoPE -> f16 q/k/v --------------------
__global__ __launch_bounds__(256) void hgemm_qkv_kernel(
    const __half* __restrict__ Ah, const __half* __restrict__ Wh,
    const float* __restrict__ bias, const float2* __restrict__ tab,
    __half* __restrict__ qout, __half* __restrict__ kout, __half* __restrict__ vout)
{
    extern __shared__ char dynsmem[];
    const uint32_t base = smem_u32(dynsmem);
    const int tid = threadIdx.x;
    const int wid = tid >> 5, lid = tid & 31;
    const int wm = wid >> 1, wn = wid & 1;
    const int m0 = blockIdx.y * 128, n0 = blockIdx.x * 128;
    const int K3 = DD;
    const __half* Ag = Ah + (size_t)m0 * K3;
    const __half* Wg = Wh + (size_t)n0 * K3;
    const int ntiles = K3 >> 5;

#define WROW_QKV(r) (Wg + (size_t)(r)*K3)
    GEMM_MAINLOOP(Ag, WROW_QKV)
#undef WROW_QKV

    // epilogue with fused RoPE: region constants (same for all nt in this warp)
    const int creg = n0 + wn*64;           // 64-aligned
    const int which = creg >> 10;
    const int hh = (creg & 1023) >> 6;
    __half* dstbase = (which == 0) ? qout : (which == 1) ? kout : vout;
    const float scl = (which == 0) ? QSCALE : 1.0f;

    #pragma unroll
    for (int mt = 0; mt < 2; mt++) {
        #pragma unroll
        for (int half = 0; half < 2; half++) {
            int n = m0 + wm*32 + mt*16 + (lid >> 2) + half*8;
            int b = n >> 11, m = n & 2047;
            __half* drow = dstbase + ((size_t)(((b << 4) + hh) * MM + m)) * DH;
            #pragma unroll
            for (int nt = 0; nt < 4; nt++) {
                int d0 = nt*8 + (lid & 3)*2;          // 0..31
                int clo = creg + d0, chi = clo + 32;
                float vlo0 = acc[mt][nt][2*half]     + bias[clo];
                float vlo1 = acc[mt][nt][2*half + 1] + bias[clo + 1];
                float vhi0 = acc[mt][nt+4][2*half]     + bias[chi];
                float vhi1 = acc[mt][nt+4][2*half + 1] + bias[chi + 1];
                if (which == 2) {
                    __half2 a; a.x = __float2half(vlo0); a.y = __float2half(vlo1);
                    __half2 c2; c2.x = __float2half(vhi0); c2.y = __float2half(vhi1);
                    *(__half2*)(drow + d0)      = a;
                    *(__half2*)(drow + d0 + 32) = c2;
                } else {
                    float2 cs0 = tab[(m << 5) | d0];
                    float2 cs1 = tab[(m << 5) | (d0 + 1)];
                    float olo0 = (vlo0 * cs0.x - vhi0 * cs0.y) * scl;
                    float ohi0 = (vlo0 * cs0.y + vhi0 * cs0.x) * scl;
                    float olo1 = (vlo1 * cs1.x - vhi1 * cs1.y) * scl;
                    float ohi1 = (vlo1 * cs1.y + vhi1 * cs1.x) * scl;
                    __half2 a; a.x = __float2half(olo0); a.y = __float2half(olo1);
                    __half2 c2; c2.x = __float2half(ohi0); c2.y = __float2half(ohi1);
                    *(__half2*)(drow + d0)      = a;
                    *(__half2*)(drow + d0 + 32) = c2;
                }
            }
        }
    }
}

// ---------------- generic f16 GEMM: fp32 C = acc + fp32 resid ------------------
__global__ __launch_bounds__(256) void hgemm_res_kernel(
    const __half* __restrict__ Ah, const __half* __restrict__ Wh,
    const float* __restrict__ resid, float* __restrict__ Cf,
    int Ndim, int K3)
{
    extern __shared__ char dynsmem[];
    const uint32_t base = smem_u32(dynsmem);
    const int tid = threadIdx.x;
    const int wid = tid >> 5, lid = tid & 31;
    const int wm = wid >> 1, wn = wid & 1;
    const int m0 = blockIdx.y * 128, n0 = blockIdx.x * 128;
    const __half* Ag = Ah + (size_t)m0 * K3;
    const __half* Wg = Wh + (size_t)n0 * K3;
    const int ntiles = K3 >> 5;

#define WROW_RES(r) (Wg + (size_t)(r)*K3)
    GEMM_MAINLOOP(Ag, WROW_RES)
#undef WROW_RES

    #pragma unroll
    for (int mt = 0; mt < 2; mt++) {
        int rbase = m0 + wm*32 + mt*16 + (lid >> 2);
        #pragma unroll
        for (int nt = 0; nt < 8; nt++) {
            int c = n0 + wn*64 + nt*8 + (lid & 3)*2;
            #pragma unroll
            for (int half = 0; half < 2; half++) {
                int n = rbase + half*8;
                const float2 rv = *(const float2*)(resid + (size_t)n * Ndim + c);
                float2 o;
                o.x = acc[mt][nt][2*half]     + rv.x;
                o.y = acc[mt][nt][2*half + 1] + rv.y;
                *(float2*)(Cf + (size_t)n * Ndim + c) = o;
            }
        }
    }
}

// ---------------- Wi GEMM + fused GeGLU -> f16 act -----------------------------
// B tile rows 0-63 = Wi[n0g..], rows 64-127 = Wi[FF+n0g..] (gate).
// wn=0 warps hold inp, wn=1 warps hold gate for the SAME act columns.
__global__ __launch_bounds__(256) void hgemm_wi_geglu_kernel(
    const __half* __restrict__ Ah, const __half* __restrict__ Wh,
    __half* __restrict__ act)
{
    extern __shared__ char dynsmem[];
    const uint32_t base = smem_u32(dynsmem);
    const int tid = threadIdx.x;
    const int wid = tid >> 5, lid = tid & 31;
    const int wm = wid >> 1, wn = wid & 1;
    const int m0 = blockIdx.y * 128;
    const int n0g = blockIdx.x * 64;           // act column base
    const int K3 = DD;
    const __half* Ag = Ah + (size_t)m0 * K3;
    const int ntiles = K3 >> 5;

#define WROW_WI(r) (Wh + (size_t)((r) < 64 ? (n0g + (r)) : (FF + n0g + (r) - 64)) * K3)
    GEMM_MAINLOOP(Ag, WROW_WI)
#undef WROW_WI

    // drain pipeline before reusing smem for the gate exchange
    asm volatile("cp.async.wait_group 0;");
    __syncthreads();

    float* gsm = (float*)dynsmem;              // [128][64] fp32 gate = 32 KB
    if (wn == 1) {
        #pragma unroll
        for (int mt = 0; mt < 2; mt++) {
            #pragma unroll
            for (int nt = 0; nt < 8; nt++) {
                int col = nt*8 + (lid & 3)*2;
                #pragma unroll
                for (int half = 0; half < 2; half++) {
                    int rl = wm*32 + mt*16 + (lid >> 2) + half*8;
                    gsm[rl*64 + col]     = acc[mt][nt][2*half];
                    gsm[rl*64 + col + 1] = acc[mt][nt][2*half + 1];
                }
            }
        }
    }
    __syncthreads();
    if (wn == 0) {
        #pragma unroll
        for (int mt = 0; mt < 2; mt++) {
            #pragma unroll
            for (int nt = 0; nt < 8; nt++) {
                int col = nt*8 + (lid & 3)*2;
                #pragma unroll
                for (int half = 0; half < 2; half++) {
                    int rl = wm*32 + mt*16 + (lid >> 2) + half*8;
                    float x0 = acc[mt][nt][2*half];
                    float x1 = acc[mt][nt][2*half + 1];
                    float gt0 = gsm[rl*64 + col];
                    float gt1 = gsm[rl*64 + col + 1];
                    float v0 = 0.5f * x0 * (1.0f + erff(x0 * 0.7071067811865476f)) * gt0;
                    float v1 = 0.5f * x1 * (1.0f + erff(x1 * 0.7071067811865476f)) * gt1;
                    __half2 hv; hv.x = __float2half(v0); hv.y = __float2half(v1);
                    *(__half2*)(act + (size_t)(m0 + rl) * FF + n0g + col) = hv;
                }
            }
        }
    }
}

// ---------------- LayerNorm -> f16 ---------------------------------------------
__inline__ __device__ float warpsum(float v) {
    #pragma unroll
    for (int o = 16; o; o >>= 1) v += __shfl_xor_sync(0xffffffff, v, o);
    return v;
}

__global__ __launch_bounds__(256) void ln_kernel(
    const float* __restrict__ x, const float* __restrict__ w,
    const float* __restrict__ b, __half* __restrict__ ah)
{
    __shared__ float red[2][8];
    int row = blockIdx.x;
    const float4* xr = (const float4*)(x + (size_t)row * DD);
    float4 v = xr[threadIdx.x];
    float s  = v.x + v.y + v.z + v.w;
    float ss = v.x*v.x + v.y*v.y + v.z*v.z + v.w*v.w;
    s = warpsum(s); ss = warpsum(ss);
    int wid = threadIdx.x >> 5, lid = threadIdx.x & 31;
    if (lid == 0) { red[0][wid] = s; red[1][wid] = ss; }
    __syncthreads();
    if (wid == 0) {
        float a = (lid < 8) ? red[0][lid] : 0.f;
        float c = (lid < 8) ? red[1][lid] : 0.f;
        a = warpsum(a); c = warpsum(c);
        if (lid == 0) { red[0][0] = a; red[1][0] = c; }
    }
    __syncthreads();
    float mean = red[0][0] * (1.0f/DD);
    float var  = red[1][0] * (1.0f/DD) - mean*mean;
    float rstd = rsqrtf(var + 1e-5f);
    float4 wv = ((const float4*)w)[threadIdx.x];
    float4 bv = ((const float4*)b)[threadIdx.x];
    float o0 = (v.x - mean)*rstd*wv.x + bv.x;
    float o1 = (v.y - mean)*rstd*wv.y + bv.y;
    float o2 = (v.z - mean)*rstd*wv.z + bv.z;
    float o3 = (v.w - mean)*rstd*wv.w + bv.w;
    __half* rowp = ah + (size_t)row * DD;
    int c = threadIdx.x * 4;
    __half2 h0; h0.x = __float2half(o0); h0.y = __float2half(o1);
    __half2 h1; h1.x = __float2half(o2); h1.y = __float2half(o3);
    *(__half2*)(rowp + c)     = h0;
    *(__half2*)(rowp + c + 2) = h1;
}

// ---------------- Flash attention: 128-query CTA, f16 mma.sync ------------------
#define ASTR 72
#define ATTN_Q_OFF 0                         // halfs
#define ATTN_K_OFF (128*ASTR)                // 9216
#define ATTN_V_OFF (ATTN_K_OFF + 2*64*ASTR)  // 18432
#define ATTN_SMEM ((ATTN_V_OFF + 2*64*ASTR) * 2)   // 55296 bytes

__global__ __launch_bounds__(256) void attn_kernel(
    const __half* __restrict__ Q2, const __half* __restrict__ K2,
    const __half* __restrict__ V2, const int* __restrict__ amask,
    __half* __restrict__ aout)
{
    extern __shared__ char dynsmem[];
    __shared__ __half2 Ms[2][32];

    const int tid = threadIdx.x, wid = tid >> 5, lid = tid & 31;
    const int bh = blockIdx.y;
    const int b = bh >> 4, h = bh & 15;
    const int q0 = blockIdx.x * 128;

    uint32_t sB = smem_u32(dynsmem);
    uint32_t qB = sB + ATTN_Q_OFF * 2;
    uint32_t kB = sB + ATTN_K_OFF * 2;
    uint32_t vB = sB + ATTN_V_OFF * 2;

    const __half* Qg = Q2 + ((size_t)bh * MM + q0) * DH;
    const __half* Kg = K2 + (size_t)bh * MM * DH;
    const __half* Vg = V2 + (size_t)bh * MM * DH;

    // preload Q (128 rows = 1024 chunks) + K0/V0 (512 chunks each) + mask0
    #pragma unroll
    for (int j = 0; j < 4; j++) {
        int idx = tid + j * 256;
        int row = idx >> 3, ch = (idx & 7) * 8;
        cp16(qB + (row*ASTR + ch)*2, Qg + row*DH + ch);
    }
    #pragma unroll
    for (int j = 0; j < 2; j++) {
        int idx = tid + j * 256;
        int row = idx >> 3, ch = (idx & 7) * 8;
        cp16(kB + (row*ASTR + ch)*2, Kg + row*DH + ch);
        cp16(vB + (row*ASTR + ch)*2, Vg + row*DH + ch);
    }
    if (tid < 32) {
        int ka = amask[b*MM + 2*tid], kb2 = amask[b*MM + 2*tid + 1];
        Ms[0][tid] = __halves2half2(__int2half_rn(ka ? 1 : 0), __int2half_rn(kb2 ? 1 : 0));
    }
    asm volatile("cp.async.commit_group;");

    float o[8][4];
    #pragma unroll
    for (int f = 0; f < 8; f++)
        #pragma unroll
        for (int j = 0; j < 4; j++) o[f][j] = 0.f;
    float lr0 = 0.f, lr1 = 0.f;

    const uint32_t aAddrBase = qB + ((uint32_t)(wid*16 + (lid & 15)) * ASTR + (lid >> 4) * 8) * 2;
    const uint32_t bRowOff = ((uint32_t)(((lid >> 4) & 1) * 8 + (lid & 7)) * ASTR + ((lid >> 3) & 1) * 8) * 2;
    const uint32_t vRowOff = ((uint32_t)(lid & 15) * ASTR + (lid >> 4) * 8) * 2;

    for (int kt = 0; kt < 32; kt++) {
        int s = kt & 1;
        if (kt + 1 < 32) {
            int s2 = s ^ 1;
            const __half* Kn = Kg + (size_t)(kt + 1) * 64 * DH;
            const __half* Vn = Vg + (size_t)(kt + 1) * 64 * DH;
            #pragma unroll
            for (int j = 0; j < 2; j++) {
                int idx = tid + j * 256;
                int row = idx >> 3, ch = (idx & 7) * 8;
                cp16(kB + (s2*64*ASTR + row*ASTR + ch)*2, Kn + row*DH + ch);
                cp16(vB + (s2*64*ASTR + row*ASTR + ch)*2, Vn + row*DH + ch);
            }
            if (tid < 32) {
                int kbase = b*MM + (kt + 1)*64;
                int ka = amask[kbase + 2*tid], kb2 = amask[kbase + 2*tid + 1];
                Ms[s2][tid] = __halves2half2(__int2half_rn(ka ? 1 : 0), __int2half_rn(kb2 ? 1 : 0));
            }
            asm volatile("cp.async.commit_group;");
            asm volatile("cp.async.wait_group 1;");
        } else {
            asm volatile("cp.async.wait_group 0;");
        }
        __syncthreads();

        uint32_t kS = kB + (uint32_t)s * 64 * ASTR * 2;
        uint32_t vS = vB + (uint32_t)s * 64 * ASTR * 2;

        float sacc[8][4];
        #pragma unroll
        for (int f = 0; f < 8; f++)
            #pragma unroll
            for (int j = 0; j < 4; j++) sacc[f][j] = 0.f;

        #pragma unroll
        for (int kk = 0; kk < 4; kk++) {
            uint32_t aq[4];
            ldm_x4(aq, aAddrBase + (uint32_t)(kk * 16) * 2);
            #pragma unroll
            for (int np = 0; np < 4; np++) {
                uint32_t bk[4];
                ldm_x4(bk, kS + (uint32_t)(np * 16) * ASTR * 2 + bRowOff + (uint32_t)(kk * 16) * 2);
                mma16816h(sacc[2*np],     aq, &bk[0]);
                mma16816h(sacc[2*np + 1], aq, &bk[2]);
            }
        }

        uint32_t p0[8], p1[8];
        __half2 l2a = __halves2half2(__float2half(0.f), __float2half(0.f));
        __half2 l2b = l2a;
        #pragma unroll
        for (int f = 0; f < 8; f++) {
            __half2 m2 = Ms[s][4*f + (lid & 3)];
            uint32_t e0u = h2exp2(cvt_h2(sacc[f][1], sacc[f][0]));
            uint32_t e1u = h2exp2(cvt_h2(sacc[f][3], sacc[f][2]));
            __half2 e0 = __hmul2(*reinterpret_cast<__half2*>(&e0u), m2);
            __half2 e1 = __hmul2(*reinterpret_cast<__half2*>(&e1u), m2);
            p0[f] = *(uint32_t*)&e0;
            p1[f] = *(uint32_t*)&e1;
            l2a = __hadd2(l2a, e0);
            l2b = __hadd2(l2b, e1);
        }
        lr0 += __low2float(l2a) + __high2float(l2a);
        lr1 += __low2float(l2b) + __high2float(l2b);

        #pragma unroll
        for (int kk = 0; kk < 4; kk++) {
            uint32_t A[4] = { p0[2*kk], p1[2*kk], p0[2*kk + 1], p1[2*kk + 1] };
            #pragma unroll
            for (int np = 0; np < 4; np++) {
                uint32_t bv[4];
                ldm_x4_t(bv, vS + (uint32_t)(kk * 16) * ASTR * 2 + vRowOff + (uint32_t)(np * 16) * 2);
                mma16816h(o[2*np],     A, &bv[0]);
                mma16816h(o[2*np + 1], A, &bv[2]);
            }
        }
        __syncthreads();
    }

    lr0 += __shfl_xor_sync(0xffffffff, lr0, 1);
    lr0 += __shfl_xor_sync(0xffffffff, lr0, 2);
    lr1 += __shfl_xor_sync(0xffffffff, lr1, 1);
    lr1 += __shfl_xor_sync(0xffffffff, lr1, 2);
    float inv0 = 1.0f / lr0, inv1 = 1.0f / lr1;

    int gm0 = q0 + wid*16 + (lid >> 2);
    int gm1 = gm0 + 8;
    __half* r0p = aout + (size_t)(b * MM + gm0) * DD + h * DH;
    __half* r1p = aout + (size_t)(b * MM + gm1) * DD + h * DH;
    #pragma unroll
    for (int f = 0; f < 8; f++) {
        int c = 8*f + (lid & 3)*2;
        __half2 w0; w0.x = __float2half(o[f][0]*inv0); w0.y = __float2half(o[f][1]*inv0);
        __half2 w1; w1.x = __float2half(o[f][2]*inv1); w1.y = __float2half(o[f][3]*inv1);
        *(__half2*)(r0p + c) = w0;
        *(__half2*)(r1p + c) = w1;
    }
}

// ---------------- launch ------------------------------------------------------
extern "C" void kernel_launch(void* const* d_in, const int* in_sizes, int n_in,
                              void* d_out, int out_size)
{
    const float* hs     = (const float*)d_in[0];
    const int*   amask  = (const int*)  d_in[1];
    const float* ln1w   = (const float*)d_in[2];
    const float* ln1b   = (const float*)d_in[3];
    const float* wqkv_w = (const float*)d_in[4];
    const float* wqkv_b = (const float*)d_in[5];
    const float* wo_w   = (const float*)d_in[6];
    const float* ln2w   = (const float*)d_in[7];
    const float* ln2b   = (const float*)d_in[8];
    const float* wi_w   = (const float*)d_in[9];
    const float* womlp  = (const float*)d_in[10];
    float* out = (float*)d_out;

    float *xres;
    float2* rtab;
    __half *xh, *wh, *act, *q2, *k2, *v2;
    cudaGetSymbolAddress((void**)&xres, g_xres);
    cudaGetSymbolAddress((void**)&rtab, g_rope);
    cudaGetSymbolAddress((void**)&xh,   g_xh);
    cudaGetSymbolAddress((void**)&wh,   g_wh);
    cudaGetSymbolAddress((void**)&act,  g_act);
    cudaGetSymbolAddress((void**)&q2,   g_q2);
    cudaGetSymbolAddress((void**)&k2,   g_k2);
    cudaGetSymbolAddress((void**)&v2,   g_v2);

    cudaFuncSetAttribute(hgemm_qkv_kernel,      cudaFuncAttributeMaxDynamicSharedMemorySize, BG_SMEM);
    cudaFuncSetAttribute(hgemm_res_kernel,      cudaFuncAttributeMaxDynamicSharedMemorySize, BG_SMEM);
    cudaFuncSetAttribute(hgemm_wi_geglu_kernel, cudaFuncAttributeMaxDynamicSharedMemorySize, BG_SMEM);
    cudaFuncSetAttribute(attn_kernel,           cudaFuncAttributeMaxDynamicSharedMemorySize, ATTN_SMEM);

    // 0. RoPE table
    ropetab_kernel<<<(MM*32)/256, 256>>>(rtab);

    // 1. LN1 -> xh (f16)
    ln_kernel<<<NTOK, 256>>>(hs, ln1w, ln1b, xh);

    // 2. QKV gemm + bias + fused RoPE -> q2/k2/v2 f16
    cvth_kernel<<<(QKV_N*DD + 255)/256, 256>>>(wqkv_w, wh, QKV_N*DD);
    hgemm_qkv_kernel<<<dim3(QKV_N/128, NTOK/128), 256, BG_SMEM>>>(
        xh, wh, wqkv_b, rtab, q2, k2, v2);

    // 3. Flash attention (128-query CTAs) -> xh f16
    attn_kernel<<<dim3(MM/128, BB*HH), 256, ATTN_SMEM>>>(q2, k2, v2, amask, xh);

    // 4. O projection + fp32 residual -> xres
    cvth_kernel<<<(DD*DD + 255)/256, 256>>>(wo_w, wh, DD*DD);
    hgemm_res_kernel<<<dim3(DD/128, NTOK/128), 256, BG_SMEM>>>(
        xh, wh, hs, xres, DD, DD);

    // 5. LN2 -> xh (f16)
    ln_kernel<<<NTOK, 256>>>(xres, ln2w, ln2b, xh);

    // 6. Wi gemm + fused GeGLU -> act f16
    cvth_kernel<<<(WI_N*DD + 255)/256, 256>>>(wi_w, wh, WI_N*DD);
    hgemm_wi_geglu_kernel<<<dim3(FF/64, NTOK/128), 256, BG_SMEM>>>(
        xh, wh, act);

    // 7. Wo_mlp gemm + fp32 residual -> out
    cvth_kernel<<<(DD*FF + 255)/256, 256>>>(womlp, wh, DD*FF);
    hgemm_res_kernel<<<dim3(DD/128, NTOK/128), 256, BG_SMEM>>>(
        act, wh, xres, out, DD, FF);
}

// round 14
// speedup vs baseline: 1.0362x; 1.0362x over previous
#include <cuda_runtime.h>
#include <cuda_bf16.h>
#include <cuda_fp16.h>
#include <math.h>
#include <stdint.h>

// Problem constants
#define BB 2
#define MM 2048
#define DD 1024
#define HH 16
#define DH 64
#define FF 2624
#define NTOK (BB*MM)           // 4096
#define QKV_N (3*DD)           // 3072
#define WI_N (2*FF)            // 5248

// ---------------- scratch (device globals; no allocation allowed) -------------
__device__ float g_xres[NTOK*DD];
__device__ float2 g_rope[MM*32];
__device__ int   g_klen[BB];
// f16 buffers
__device__ __align__(128) __half g_xh [(size_t)NTOK*DD];     // LN1/attn/LN2 out
__device__ __align__(128) __half g_wh [(size_t)WI_N*DD];     // current weight, f16
__device__ __align__(128) __half g_gg [(size_t)NTOK*WI_N];   // wi out f16
__device__ __align__(128) __half g_act[(size_t)NTOK*FF];     // geglu out f16
__device__ __align__(128) __half g_q2[(size_t)BB*HH*MM*DH];
__device__ __align__(128) __half g_k2[(size_t)BB*HH*MM*DH];
__device__ __align__(128) __half g_v2[(size_t)BB*HH*MM*DH];

// ---------------- PTX helpers ---------------------------------------------------
__device__ __forceinline__ uint32_t smem_u32(const void* p) {
    uint32_t a;
    asm("{ .reg .u64 t; cvta.to.shared.u64 t, %1; cvt.u32.u64 %0, t; }"
        : "=r"(a) : "l"(p));
    return a;
}
__device__ __forceinline__ void cp16(uint32_t saddr, const void* g) {
    asm volatile("cp.async.cg.shared.global [%0], [%1], 16;" :: "r"(saddr), "l"(g));
}
__device__ __forceinline__ void ldm_x4(uint32_t* r, uint32_t addr) {
    asm volatile("ldmatrix.sync.aligned.m8n8.x4.shared.b16 {%0,%1,%2,%3}, [%4];"
        : "=r"(r[0]), "=r"(r[1]), "=r"(r[2]), "=r"(r[3]) : "r"(addr));
}
__device__ __forceinline__ void ldm_x4_t(uint32_t* r, uint32_t addr) {
    asm volatile("ldmatrix.sync.aligned.m8n8.x4.trans.shared.b16 {%0,%1,%2,%3}, [%4];"
        : "=r"(r[0]), "=r"(r[1]), "=r"(r[2]), "=r"(r[3]) : "r"(addr));
}
__device__ __forceinline__ void mma16816h(float* c, const uint32_t* a, const uint32_t* b) {
    asm volatile("mma.sync.aligned.m16n8k16.row.col.f32.f16.f16.f32 "
        "{%0,%1,%2,%3}, {%4,%5,%6,%7}, {%8,%9}, {%0,%1,%2,%3};"
        : "+f"(c[0]), "+f"(c[1]), "+f"(c[2]), "+f"(c[3])
        : "r"(a[0]), "r"(a[1]), "r"(a[2]), "r"(a[3]), "r"(b[0]), "r"(b[1]));
}
__device__ __forceinline__ uint32_t cvt_h2(float hi, float lo) {
    uint32_t d;
    asm("cvt.rn.f16x2.f32 %0, %1, %2;" : "=r"(d) : "f"(hi), "f"(lo));
    return d;
}
__device__ __forceinline__ uint32_t h2exp2(uint32_t x) {
    uint32_t d;
    asm("ex2.approx.f16x2 %0, %1;" : "=r"(d) : "r"(x));
    return d;
}

// ---------------- small prep kernels --------------------------------------------
__global__ void cvth_kernel(const float* __restrict__ X, __half* __restrict__ Y, int total)
{
    int i = blockIdx.x * 256 + threadIdx.x;
    if (i < total) Y[i] = __float2half(X[i]);
}

__global__ void ropetab_kernel(float2* __restrict__ tab)
{
    int gid = blockIdx.x * 256 + threadIdx.x;     // over MM*32
    int i = gid & 31;
    int m = gid >> 5;
    float invf = (float)exp2(-(double)i * (13.287712379549449 / 32.0));
    float angle = (float)m * invf;
    float sv, cv;
    sincosf(angle, &sv, &cv);
    tab[gid] = make_float2(cv, sv);
}

// one warp per batch: count valid keys
__global__ void klen_kernel(const int* __restrict__ amask, int* __restrict__ klen)
{
    int b = blockIdx.x;
    int s = 0;
    for (int i = threadIdx.x; i < MM; i += 32)
        s += (amask[b*MM + i] != 0);
    #pragma unroll
    for (int o = 16; o; o >>= 1) s += __shfl_xor_sync(0xffffffff, s, o);
    if (threadIdx.x == 0) klen[b] = s;
}

// ---------------- shared GEMM config (128x128, 4-stage) -------------------------
#define PADK 40
#define STAGES 4
#define AB_BYTES (128*PADK*2)               // 10240
#define STAGE_BYTES (2*AB_BYTES)            // 20480
#define BG_SMEM (STAGES*STAGE_BYTES)        // 81920
#define QSCALE 0.18033688011112042f         // 0.125 * log2(e)

#define GEMM_MAINLOOP(AGPTR, WROW_EXPR)                                            \
    const int ldr0 = tid >> 2, ldc0 = (tid & 3) * 8;                               \
    const int ldr1 = (tid + 256) >> 2;                                             \
    const uint32_t so0 = (uint32_t)(ldr0*PADK + ldc0) * 2;                         \
    const uint32_t so1 = (uint32_t)(ldr1*PADK + ldc0) * 2;                         \
    float acc[2][8][4];                                                            \
    _Pragma("unroll")                                                              \
    for (int i = 0; i < 2; i++)                                                    \
        _Pragma("unroll")                                                          \
        for (int j = 0; j < 8; j++)                                                \
            _Pragma("unroll")                                                      \
            for (int x = 0; x < 4; x++) acc[i][j][x] = 0.f;                        \
    const int aRowOff0 = (wm*32 + (lid & 15)) * PADK + (lid >> 4) * 8;             \
    const int aRowOff1 = aRowOff0 + 16 * PADK;                                     \
    const int bRowBase = (wn*64 + ((lid >> 4) & 1) * 8 + (lid & 7)) * PADK         \
                       + ((lid >> 3) & 1) * 8;                                     \
    _Pragma("unroll")                                                              \
    for (int t = 0; t < STAGES - 1; t++) {                                         \
        uint32_t sb = base + (uint32_t)t * STAGE_BYTES;                            \
        cp16(sb + so0,            AGPTR + (size_t)ldr0*K3 + t*32 + ldc0);          \
        cp16(sb + AB_BYTES + so0, WROW_EXPR(ldr0) + t*32 + ldc0);                  \
        cp16(sb + so1,            AGPTR + (size_t)ldr1*K3 + t*32 + ldc0);          \
        cp16(sb + AB_BYTES + so1, WROW_EXPR(ldr1) + t*32 + ldc0);                  \
        asm volatile("cp.async.commit_group;");                                    \
    }                                                                              \
    for (int t = 0; t < ntiles; t++) {                                             \
        asm volatile("cp.async.wait_group %0;" :: "n"(STAGES - 2));                \
        __syncthreads();                                                           \
        if (t + STAGES - 1 < ntiles) {                                             \
            int tp = t + STAGES - 1;                                               \
            uint32_t sb = base + (uint32_t)(tp & (STAGES-1)) * STAGE_BYTES;        \
            cp16(sb + so0,            AGPTR + (size_t)ldr0*K3 + tp*32 + ldc0);     \
            cp16(sb + AB_BYTES + so0, WROW_EXPR(ldr0) + tp*32 + ldc0);             \
            cp16(sb + so1,            AGPTR + (size_t)ldr1*K3 + tp*32 + ldc0);     \
            cp16(sb + AB_BYTES + so1, WROW_EXPR(ldr1) + tp*32 + ldc0);             \
        }                                                                          \
        asm volatile("cp.async.commit_group;");                                    \
        uint32_t aS = base + (uint32_t)(t & (STAGES-1)) * STAGE_BYTES;             \
        uint32_t bS = aS + AB_BYTES;                                               \
        _Pragma("unroll")                                                          \
        for (int ks = 0; ks < 2; ks++) {                                           \
            uint32_t afr[2][4];                                                    \
            ldm_x4(afr[0], aS + (uint32_t)(aRowOff0 + ks*16) * 2);                 \
            ldm_x4(afr[1], aS + (uint32_t)(aRowOff1 + ks*16) * 2);                 \
            uint32_t bfr[4][4];                                                    \
            _Pragma("unroll")                                                      \
            for (int np = 0; np < 4; np++)                                         \
                ldm_x4(bfr[np], bS + (uint32_t)(bRowBase + np*16*PADK + ks*16) * 2); \
            _Pragma("unroll")                                                      \
            for (int mt = 0; mt < 2; mt++)                                         \
                _Pragma("unroll")                                                  \
                for (int np = 0; np < 4; np++) {                                   \
                    mma16816h(acc[mt][2*np],     afr[mt], &bfr[np][0]);            \
                    mma16816h(acc[mt][2*np + 1], afr[mt], &bfr[np][2]);            \
                }                                                                  \
        }                                                                          \
    }

// ---------------- QKV GEMM + bias + fused RoPE -> f16 q/k/v --------------------
__global__ __launch_bounds__(256) void hgemm_qkv_kernel(
    const __half* __restrict__ Ah, const __half* __restrict__ Wh,
    const float* __restrict__ bias, const float2* __restrict__ tab,
    __half* __restrict__ qout, __half* __restrict__ kout, __half* __restrict__ vout)
{
    extern __shared__ char dynsmem[];
    const uint32_t base = smem_u32(dynsmem);
    const int tid = threadIdx.x;
    const int wid = tid >> 5, lid = tid & 31;
    const int wm = wid >> 1, wn = wid & 1;
    const int m0 = blockIdx.y * 128, n0 = blockIdx.x * 128;
    const int K3 = DD;
    const __half* Ag = Ah + (size_t)m0 * K3;
    const __half* Wg = Wh + (size_t)n0 * K3;
    const int ntiles = K3 >> 5;

#define WROW_QKV(r) (Wg + (size_t)(r)*K3)
    GEMM_MAINLOOP(Ag, WROW_QKV)
#undef WROW_QKV

    const int creg = n0 + wn*64;           // 64-aligned
    const int which = creg >> 10;
    const int hh = (creg & 1023) >> 6;
    __half* dstbase = (which == 0) ? qout : (which == 1) ? kout : vout;
    const float scl = (which == 0) ? QSCALE : 1.0f;

    #pragma unroll
    for (int mt = 0; mt < 2; mt++) {
        #pragma unroll
        for (int half = 0; half < 2; half++) {
            int n = m0 + wm*32 + mt*16 + (lid >> 2) + half*8;
            int b = n >> 11, m = n & 2047;
            __half* drow = dstbase + ((size_t)(((b << 4) + hh) * MM + m)) * DH;
            #pragma unroll
            for (int nt = 0; nt < 4; nt++) {
                int d0 = nt*8 + (lid & 3)*2;          // 0..31
                int clo = creg + d0, chi = clo + 32;
                float vlo0 = acc[mt][nt][2*half]     + bias[clo];
                float vlo1 = acc[mt][nt][2*half + 1] + bias[clo + 1];
                float vhi0 = acc[mt][nt+4][2*half]     + bias[chi];
                float vhi1 = acc[mt][nt+4][2*half + 1] + bias[chi + 1];
                if (which == 2) {
                    __half2 a; a.x = __float2half(vlo0); a.y = __float2half(vlo1);
                    __half2 c2; c2.x = __float2half(vhi0); c2.y = __float2half(vhi1);
                    *(__half2*)(drow + d0)      = a;
                    *(__half2*)(drow + d0 + 32) = c2;
                } else {
                    float2 cs0 = tab[(m << 5) | d0];
                    float2 cs1 = tab[(m << 5) | (d0 + 1)];
                    float olo0 = (vlo0 * cs0.x - vhi0 * cs0.y) * scl;
                    float ohi0 = (vlo0 * cs0.y + vhi0 * cs0.x) * scl;
                    float olo1 = (vlo1 * cs1.x - vhi1 * cs1.y) * scl;
                    float ohi1 = (vlo1 * cs1.y + vhi1 * cs1.x) * scl;
                    __half2 a; a.x = __float2half(olo0); a.y = __float2half(olo1);
                    __half2 c2; c2.x = __float2half(ohi0); c2.y = __float2half(ohi1);
                    *(__half2*)(drow + d0)      = a;
                    *(__half2*)(drow + d0 + 32) = c2;
                }
            }
        }
    }
}

// ---------------- generic f16 GEMM: fp32 C = acc + fp32 resid ------------------
__global__ __launch_bounds__(256) void hgemm_res_kernel(
    const __half* __restrict__ Ah, const __half* __restrict__ Wh,
    const float* __restrict__ resid, float* __restrict__ Cf,
    int Ndim, int K3)
{
    extern __shared__ char dynsmem[];
    const uint32_t base = smem_u32(dynsmem);
    const int tid = threadIdx.x;
    const int wid = tid >> 5, lid = tid & 31;
    const int wm = wid >> 1, wn = wid & 1;
    const int m0 = blockIdx.y * 128, n0 = blockIdx.x * 128;
    const __half* Ag = Ah + (size_t)m0 * K3;
    const __half* Wg = Wh + (size_t)n0 * K3;
    const int ntiles = K3 >> 5;

#define WROW_RES(r) (Wg + (size_t)(r)*K3)
    GEMM_MAINLOOP(Ag, WROW_RES)
#undef WROW_RES

    #pragma unroll
    for (int mt = 0; mt < 2; mt++) {
        int rbase = m0 + wm*32 + mt*16 + (lid >> 2);
        #pragma unroll
        for (int nt = 0; nt < 8; nt++) {
            int c = n0 + wn*64 + nt*8 + (lid & 3)*2;
            #pragma unroll
            for (int half = 0; half < 2; half++) {
                int n = rbase + half*8;
                const float2 rv = *(const float2*)(resid + (size_t)n * Ndim + c);
                float2 o;
                o.x = acc[mt][nt][2*half]     + rv.x;
                o.y = acc[mt][nt][2*half + 1] + rv.y;
                *(float2*)(Cf + (size_t)n * Ndim + c) = o;
            }
        }
    }
}

// ---------------- f16 GEMM: f16 C = acc (Wi) -----------------------------------
__global__ __launch_bounds__(256) void hgemm_h_kernel(
    const __half* __restrict__ Ah, const __half* __restrict__ Wh,
    __half* __restrict__ Chalf, int Ndim, int K3)
{
    extern __shared__ char dynsmem[];
    const uint32_t base = smem_u32(dynsmem);
    const int tid = threadIdx.x;
    const int wid = tid >> 5, lid = tid & 31;
    const int wm = wid >> 1, wn = wid & 1;
    const int m0 = blockIdx.y * 128, n0 = blockIdx.x * 128;
    const __half* Ag = Ah + (size_t)m0 * K3;
    const __half* Wg = Wh + (size_t)n0 * K3;
    const int ntiles = K3 >> 5;

#define WROW_H(r) (Wg + (size_t)(r)*K3)
    GEMM_MAINLOOP(Ag, WROW_H)
#undef WROW_H

    #pragma unroll
    for (int mt = 0; mt < 2; mt++) {
        int rbase = m0 + wm*32 + mt*16 + (lid >> 2);
        #pragma unroll
        for (int nt = 0; nt < 8; nt++) {
            int c = n0 + wn*64 + nt*8 + (lid & 3)*2;
            #pragma unroll
            for (int half = 0; half < 2; half++) {
                int n = rbase + half*8;
                __half2 hv;
                hv.x = __float2half(acc[mt][nt][2*half]);
                hv.y = __float2half(acc[mt][nt][2*half + 1]);
                *(__half2*)(Chalf + (size_t)n * Ndim + c) = hv;
            }
        }
    }
}

// ---------------- LayerNorm -> f16 ---------------------------------------------
__inline__ __device__ float warpsum(float v) {
    #pragma unroll
    for (int o = 16; o; o >>= 1) v += __shfl_xor_sync(0xffffffff, v, o);
    return v;
}

__global__ __launch_bounds__(256) void ln_kernel(
    const float* __restrict__ x, const float* __restrict__ w,
    const float* __restrict__ b, __half* __restrict__ ah)
{
    __shared__ float red[2][8];
    int row = blockIdx.x;
    const float4* xr = (const float4*)(x + (size_t)row * DD);
    float4 v = xr[threadIdx.x];
    float s  = v.x + v.y + v.z + v.w;
    float ss = v.x*v.x + v.y*v.y + v.z*v.z + v.w*v.w;
    s = warpsum(s); ss = warpsum(ss);
    int wid = threadIdx.x >> 5, lid = threadIdx.x & 31;
    if (lid == 0) { red[0][wid] = s; red[1][wid] = ss; }
    __syncthreads();
    if (wid == 0) {
        float a = (lid < 8) ? red[0][lid] : 0.f;
        float c = (lid < 8) ? red[1][lid] : 0.f;
        a = warpsum(a); c = warpsum(c);
        if (lid == 0) { red[0][0] = a; red[1][0] = c; }
    }
    __syncthreads();
    float mean = red[0][0] * (1.0f/DD);
    float var  = red[1][0] * (1.0f/DD) - mean*mean;
    float rstd = rsqrtf(var + 1e-5f);
    float4 wv = ((const float4*)w)[threadIdx.x];
    float4 bv = ((const float4*)b)[threadIdx.x];
    float o0 = (v.x - mean)*rstd*wv.x + bv.x;
    float o1 = (v.y - mean)*rstd*wv.y + bv.y;
    float o2 = (v.z - mean)*rstd*wv.z + bv.z;
    float o3 = (v.w - mean)*rstd*wv.w + bv.w;
    __half* rowp = ah + (size_t)row * DD;
    int c = threadIdx.x * 4;
    __half2 h0; h0.x = __float2half(o0); h0.y = __float2half(o1);
    __half2 h1; h1.x = __float2half(o2); h1.y = __float2half(o3);
    *(__half2*)(rowp + c)     = h0;
    *(__half2*)(rowp + c + 2) = h1;
}

// ---------------- Flash attention: 64-query CTA, dynamic key-tile count ---------
#define ASTR 72
__global__ __launch_bounds__(128) void attn_kernel(
    const __half* __restrict__ Q2, const __half* __restrict__ K2,
    const __half* __restrict__ V2, const int* __restrict__ amask,
    const int* __restrict__ klen, __half* __restrict__ aout)
{
    __shared__ __half Qs[64][ASTR];
    __shared__ __half Ks[2][64][ASTR];
    __shared__ __half Vs[2][64][ASTR];
    __shared__ __half2 Ms[2][32];

    const int tid = threadIdx.x, wid = tid >> 5, lid = tid & 31;
    const int bh = blockIdx.y;
    const int b = bh >> 4, h = bh & 15;
    const int q0 = blockIdx.x * 64;
    const int ntk = (klen[b] + 63) >> 6;        // valid key tiles

    uint32_t qB = smem_u32(Qs);
    uint32_t kB = smem_u32(Ks);
    uint32_t vB = smem_u32(Vs);

    const __half* Qg = Q2 + ((size_t)bh * MM + q0) * DH;
    const __half* Kg = K2 + (size_t)bh * MM * DH;
    const __half* Vg = V2 + (size_t)bh * MM * DH;

    #pragma unroll
    for (int j = 0; j < 4; j++) {
        int idx = tid + j * 128;
        int row = idx >> 3, ch = (idx & 7) * 8;
        cp16(qB + (row*ASTR + ch)*2, Qg + row*DH + ch);
        cp16(kB + (row*ASTR + ch)*2, Kg + row*DH + ch);
        cp16(vB + (row*ASTR + ch)*2, Vg + row*DH + ch);
    }
    if (tid < 32) {
        int ka = amask[b*MM + 2*tid], kb2 = amask[b*MM + 2*tid + 1];
        Ms[0][tid] = __halves2half2(__int2half_rn(ka ? 1 : 0), __int2half_rn(kb2 ? 1 : 0));
    }
    asm volatile("cp.async.commit_group;");

    float o[8][4];
    #pragma unroll
    for (int f = 0; f < 8; f++)
        #pragma unroll
        for (int j = 0; j < 4; j++) o[f][j] = 0.f;
    float lr0 = 0.f, lr1 = 0.f;

    const uint32_t aAddrBase = qB + ((uint32_t)(wid*16 + (lid & 15)) * ASTR + (lid >> 4) * 8) * 2;
    const uint32_t bRowOff = ((uint32_t)(((lid >> 4) & 1) * 8 + (lid & 7)) * ASTR + ((lid >> 3) & 1) * 8) * 2;
    const uint32_t vRowOff = ((uint32_t)(lid & 15) * ASTR + (lid >> 4) * 8) * 2;

    for (int kt = 0; kt < ntk; kt++) {
        int s = kt & 1;
        if (kt + 1 < ntk) {
            int s2 = s ^ 1;
            const __half* Kn = Kg + (size_t)(kt + 1) * 64 * DH;
            const __half* Vn = Vg + (size_t)(kt + 1) * 64 * DH;
            #pragma unroll
            for (int j = 0; j < 4; j++) {
                int idx = tid + j * 128;
                int row = idx >> 3, ch = (idx & 7) * 8;
                cp16(kB + (s2*64*ASTR + row*ASTR + ch)*2, Kn + row*DH + ch);
                cp16(vB + (s2*64*ASTR + row*ASTR + ch)*2, Vn + row*DH + ch);
            }
            if (tid < 32) {
                int kbase = b*MM + (kt + 1)*64;
                int ka = amask[kbase + 2*tid], kb2 = amask[kbase + 2*tid + 1];
                Ms[s2][tid] = __halves2half2(__int2half_rn(ka ? 1 : 0), __int2half_rn(kb2 ? 1 : 0));
            }
            asm volatile("cp.async.commit_group;");
            asm volatile("cp.async.wait_group 1;");
        } else {
            asm volatile("cp.async.wait_group 0;");
        }
        __syncthreads();

        uint32_t kS = kB + (uint32_t)s * 64 * ASTR * 2;
        uint32_t vS = vB + (uint32_t)s * 64 * ASTR * 2;

        float sacc[8][4];
        #pragma unroll
        for (int f = 0; f < 8; f++)
            #pragma unroll
            for (int j = 0; j < 4; j++) sacc[f][j] = 0.f;

        #pragma unroll
        for (int kk = 0; kk < 4; kk++) {
            uint32_t aq[4];
            ldm_x4(aq, aAddrBase + (uint32_t)(kk * 16) * 2);
            #pragma unroll
            for (int np = 0; np < 4; np++) {
                uint32_t bk[4];
                ldm_x4(bk, kS + (uint32_t)(np * 16) * ASTR * 2 + bRowOff + (uint32_t)(kk * 16) * 2);
                mma16816h(sacc[2*np],     aq, &bk[0]);
                mma16816h(sacc[2*np + 1], aq, &bk[2]);
            }
        }

        uint32_t p0[8], p1[8];
        __half2 l2a = __halves2half2(__float2half(0.f), __float2half(0.f));
        __half2 l2b = l2a;
        #pragma unroll
        for (int f = 0; f < 8; f++) {
            __half2 m2 = Ms[s][4*f + (lid & 3)];
            uint32_t e0u = h2exp2(cvt_h2(sacc[f][1], sacc[f][0]));
            uint32_t e1u = h2exp2(cvt_h2(sacc[f][3], sacc[f][2]));
            __half2 e0 = __hmul2(*reinterpret_cast<__half2*>(&e0u), m2);
            __half2 e1 = __hmul2(*reinterpret_cast<__half2*>(&e1u), m2);
            p0[f] = *(uint32_t*)&e0;
            p1[f] = *(uint32_t*)&e1;
            l2a = __hadd2(l2a, e0);
            l2b = __hadd2(l2b, e1);
        }
        lr0 += __low2float(l2a) + __high2float(l2a);
        lr1 += __low2float(l2b) + __high2float(l2b);

        #pragma unroll
        for (int kk = 0; kk < 4; kk++) {
            uint32_t A[4] = { p0[2*kk], p1[2*kk], p0[2*kk + 1], p1[2*kk + 1] };
            #pragma unroll
            for (int np = 0; np < 4; np++) {
                uint32_t bv[4];
                ldm_x4_t(bv, vS + (uint32_t)(kk * 16) * ASTR * 2 + vRowOff + (uint32_t)(np * 16) * 2);
                mma16816h(o[2*np],     A, &bv[0]);
                mma16816h(o[2*np + 1], A, &bv[2]);
            }
        }
        __syncthreads();
    }

    lr0 += __shfl_xor_sync(0xffffffff, lr0, 1);
    lr0 += __shfl_xor_sync(0xffffffff, lr0, 2);
    lr1 += __shfl_xor_sync(0xffffffff, lr1, 1);
    lr1 += __shfl_xor_sync(0xffffffff, lr1, 2);
    float inv0 = 1.0f / lr0, inv1 = 1.0f / lr1;

    int gm0 = q0 + wid*16 + (lid >> 2);
    int gm1 = gm0 + 8;
    __half* r0p = aout + (size_t)(b * MM + gm0) * DD + h * DH;
    __half* r1p = aout + (size_t)(b * MM + gm1) * DD + h * DH;
    #pragma unroll
    for (int f = 0; f < 8; f++) {
        int c = 8*f + (lid & 3)*2;
        __half2 w0; w0.x = __float2half(o[f][0]*inv0); w0.y = __float2half(o[f][1]*inv0);
        __half2 w1; w1.x = __float2half(o[f][2]*inv1); w1.y = __float2half(o[f][3]*inv1);
        *(__half2*)(r0p + c) = w0;
        *(__half2*)(r1p + c) = w1;
    }
}

// ---------------- GeGLU f16 -> f16 ---------------------------------------------
__global__ void geglu_kernel(const __half* __restrict__ g, __half* __restrict__ act)
{
    int n = blockIdx.x;
    const __half2* gr = (const __half2*)(g + (size_t)n * WI_N);
    __half2* ar = (__half2*)(act + (size_t)n * FF);
    for (int f2 = threadIdx.x; f2 < FF/2; f2 += blockDim.x) {
        float2 x2 = __half22float2(gr[f2]);
        float2 gt = __half22float2(gr[f2 + FF/2]);
        float v0 = 0.5f * x2.x * (1.0f + erff(x2.x * 0.7071067811865476f)) * gt.x;
        float v1 = 0.5f * x2.y * (1.0f + erff(x2.y * 0.7071067811865476f)) * gt.y;
        __half2 hv; hv.x = __float2half(v0); hv.y = __float2half(v1);
        ar[f2] = hv;
    }
}

// ---------------- launch ------------------------------------------------------
extern "C" void kernel_launch(void* const* d_in, const int* in_sizes, int n_in,
                              void* d_out, int out_size)
{
    const float* hs     = (const float*)d_in[0];
    const int*   amask  = (const int*)  d_in[1];
    const float* ln1w   = (const float*)d_in[2];
    const float* ln1b   = (const float*)d_in[3];
    const float* wqkv_w = (const float*)d_in[4];
    const float* wqkv_b = (const float*)d_in[5];
    const float* wo_w   = (const float*)d_in[6];
    const float* ln2w   = (const float*)d_in[7];
    const float* ln2b   = (const float*)d_in[8];
    const float* wi_w   = (const float*)d_in[9];
    const float* womlp  = (const float*)d_in[10];
    float* out = (float*)d_out;

    float *xres;
    float2* rtab;
    int* klen;
    __half *xh, *wh, *gg, *act, *q2, *k2, *v2;
    cudaGetSymbolAddress((void**)&xres, g_xres);
    cudaGetSymbolAddress((void**)&rtab, g_rope);
    cudaGetSymbolAddress((void**)&klen, g_klen);
    cudaGetSymbolAddress((void**)&xh,   g_xh);
    cudaGetSymbolAddress((void**)&wh,   g_wh);
    cudaGetSymbolAddress((void**)&gg,   g_gg);
    cudaGetSymbolAddress((void**)&act,  g_act);
    cudaGetSymbolAddress((void**)&q2,   g_q2);
    cudaGetSymbolAddress((void**)&k2,   g_k2);
    cudaGetSymbolAddress((void**)&v2,   g_v2);

    cudaFuncSetAttribute(hgemm_qkv_kernel, cudaFuncAttributeMaxDynamicSharedMemorySize, BG_SMEM);
    cudaFuncSetAttribute(hgemm_res_kernel, cudaFuncAttributeMaxDynamicSharedMemorySize, BG_SMEM);
    cudaFuncSetAttribute(hgemm_h_kernel,   cudaFuncAttributeMaxDynamicSharedMemorySize, BG_SMEM);

    // 0. RoPE table + key lengths
    ropetab_kernel<<<(MM*32)/256, 256>>>(rtab);
    klen_kernel<<<BB, 32>>>(amask, klen);

    // 1. LN1 -> xh (f16)
    ln_kernel<<<NTOK, 256>>>(hs, ln1w, ln1b, xh);

    // 2. QKV gemm + bias + fused RoPE -> q2/k2/v2 f16
    cvth_kernel<<<(QKV_N*DD + 255)/256, 256>>>(wqkv_w, wh, QKV_N*DD);
    hgemm_qkv_kernel<<<dim3(QKV_N/128, NTOK/128), 256, BG_SMEM>>>(
        xh, wh, wqkv_b, rtab, q2, k2, v2);

    // 3. Flash attention (64-query CTAs, valid-tile loop) -> xh f16
    attn_kernel<<<dim3(MM/64, BB*HH), 128>>>(q2, k2, v2, amask, klen, xh);

    // 4. O projection + fp32 residual -> xres
    cvth_kernel<<<(DD*DD + 255)/256, 256>>>(wo_w, wh, DD*DD);
    hgemm_res_kernel<<<dim3(DD/128, NTOK/128), 256, BG_SMEM>>>(
        xh, wh, hs, xres, DD, DD);

    // 5. LN2 -> xh (f16)
    ln_kernel<<<NTOK, 256>>>(xres, ln2w, ln2b, xh);

    // 6. Wi gemm -> gg f16
    cvth_kernel<<<(WI_N*DD + 255)/256, 256>>>(wi_w, wh, WI_N*DD);
    hgemm_h_kernel<<<dim3(WI_N/128, NTOK/128), 256, BG_SMEM>>>(
        xh, wh, gg, WI_N, DD);

    // 7. GeGLU -> act f16
    geglu_kernel<<<NTOK, 256>>>(gg, act);

    // 8. Wo_mlp gemm + fp32 residual -> out
    cvth_kernel<<<(DD*FF + 255)/256, 256>>>(womlp, wh, DD*FF);
    hgemm_res_kernel<<<dim3(DD/128, NTOK/128), 256, BG_SMEM>>>(
        act, wh, xres, out, DD, FF);
}